// round 15
// baseline (speedup 1.0000x reference)
#include <cuda_runtime.h>

// Problem constants (fixed by the dataset)
#define NB    128          // graphs (B)
#define NN    256          // nodes per graph
#define DPE   16           // D_pe / eigen dim
#define MM    4            // M psi copies
#define HPSI  32
#define HP    16
#define HG    64
#define NSUM  (NB*NN)      // 32768
#define EDGES (NSUM*16)    // 524288
#define EPG   (EDGES/NB)   // 4096 edges per graph (graph-contiguous)
#define VPAD  20           // padded row stride (floats)

typedef unsigned long long u64;

// ---------------- packed f32x2 helpers ----------------
__device__ __forceinline__ u64 pk2(float lo, float hi) {
    u64 r; asm("mov.b64 %0,{%1,%2};" : "=l"(r) : "f"(lo), "f"(hi)); return r;
}
__device__ __forceinline__ void upk2(u64 v, float& lo, float& hi) {
    asm("mov.b64 {%0,%1},%2;" : "=f"(lo), "=f"(hi) : "l"(v));
}
__device__ __forceinline__ u64 fma2(u64 a, u64 b, u64 c) {
    u64 d; asm("fma.rn.f32x2 %0,%1,%2,%3;" : "=l"(d) : "l"(a), "l"(b), "l"(c)); return d;
}
__device__ __forceinline__ u64 mul2(u64 a, u64 b) {
    u64 d; asm("mul.rn.f32x2 %0,%1,%2;" : "=l"(d) : "l"(a), "l"(b)); return d;
}
__device__ __forceinline__ u64 add2(u64 a, u64 b) {
    u64 d; asm("add.rn.f32x2 %0,%1,%2;" : "=l"(d) : "l"(a), "l"(b)); return d;
}

// ---------------------------------------------------------------------------
// ONE fused kernel per graph, 512 threads: node n handled by threads n and
// n+256 (offset split: each handles 2 of the 4 offsets per barrier group).
// CSR build -> psi/mask -> o-loop -> combine -> in-smem GIN gather + MLP.
// ---------------------------------------------------------------------------
#define COMPUTE_R2(kk) do {                                                     \
    const ulonglong2* vr_ = (const ulonglong2*)&Vs[(kk)*VPAD];                  \
    ulonglong2 a_ = vr_[0], b_ = vr_[1], c_ = vr_[2], d_ = vr_[3];              \
    u64 vk_[8] = {a_.x, a_.y, b_.x, b_.y, c_.x, c_.y, d_.x, d_.y};              \
    u64 wm_[4];                                                                 \
    _Pragma("unroll")                                                           \
    for (int m_ = 0; m_ < 4; m_++) {                                            \
        u64 s_ = mul2(An2[m_][0], vk_[0]);                                      \
        _Pragma("unroll")                                                       \
        for (int j_ = 1; j_ < 8; j_++) s_ = fma2(An2[m_][j_], vk_[j_], s_);     \
        float lo_, hi_; upk2(s_, lo_, hi_);                                     \
        float w_ = lo_ + hi_;                                                   \
        wm_[m_] = pk2(w_, w_);                                                  \
    }                                                                           \
    _Pragma("unroll")                                                           \
    for (int hp_ = 0; hp_ < 8; hp_++) {                                         \
        u64 p_ = fma2(wm_[0], wp2[0][hp_], bps2[hp_]);                          \
        p_ = fma2(wm_[1], wp2[1][hp_], p_);                                     \
        p_ = fma2(wm_[2], wp2[2][hp_], p_);                                     \
        p_ = fma2(wm_[3], wp2[3][hp_], p_);                                     \
        float lo_, hi_; upk2(p_, lo_, hi_);                                     \
        lo_ = fmaxf(lo_, 0.f); hi_ = fmaxf(hi_, 0.f);                           \
        rp[hp_] = pk2(lo_, hi_);                                                \
    }                                                                           \
} while (0)

#define BODY_WRITE(oo, bufrow) do {                                             \
    int k_ = (node + (oo)) & 255;                                               \
    COMPUTE_R2(k_);                                                             \
    u64* xw_ = (u64*)(bufrow);                                                  \
    _Pragma("unroll")                                                           \
    for (int h_ = 0; h_ < 8; h_++) {                                            \
        acc2[h_] = add2(acc2[h_], rp[h_]);                                      \
        xw_[h_] = rp[h_];                                                       \
    }                                                                           \
} while (0)

#define BODY_READ(oo, bufbase) do {                                             \
    int p_ = (node - (oo)) & 255;                                               \
    const ulonglong2* xr_ = (const ulonglong2*)&(bufbase)[p_*VPAD];             \
    ulonglong2 a0_ = xr_[0], a1_ = xr_[1], a2_ = xr_[2], a3_ = xr_[3];          \
    acc2[0] = add2(acc2[0], a0_.x); acc2[1] = add2(acc2[1], a0_.y);             \
    acc2[2] = add2(acc2[2], a1_.x); acc2[3] = add2(acc2[3], a1_.y);             \
    acc2[4] = add2(acc2[4], a2_.x); acc2[5] = add2(acc2[5], a2_.y);             \
    acc2[6] = add2(acc2[6], a3_.x); acc2[7] = add2(acc2[7], a3_.y);             \
} while (0)

__global__ void __launch_bounds__(512) kernelF(
        const float* __restrict__ V,
        const float* __restrict__ Lambda,
        const float* __restrict__ pW1, const float* __restrict__ pb1,
        const float* __restrict__ pW2, const float* __restrict__ pb2,
        const float* __restrict__ Wp1, const float* __restrict__ bp1,
        const float* __restrict__ Wg1, const float* __restrict__ bg1,
        const float* __restrict__ Wg2, const float* __restrict__ bg2,
        const float* __restrict__ eps,
        const int*   __restrict__ batch,
        const int*   __restrict__ edge_index,
        float* __restrict__ out)
{
    extern __shared__ float sm[];
    // Persistent regions
    float* Vs      = sm;                         // 5120 floats
    float* xch     = sm + NN*VPAD;               // 8 buffers x 5120
    float* zs      = sm + 9*NN*VPAD;             // 64
    int*   srt_s   = (int*)(sm + 9*NN*VPAD + 64);        // 4096 ints
    int*   start_s = (int*)(sm + 9*NN*VPAD + 64 + 4096); // 257 ints
    __shared__ int bnds[2];
    __shared__ int wsum[8];

    // Phase-limited aliases (CSR build) inside xch:
    int* cnt  = (int*)xch;          // 256
    int* cur  = cnt + NN;           // 256
    int* dstc = cur + NN;           // 4096

    // Phase-limited aliases (epilogue) inside xch:
    float* xT   = xch;              // 5120 (x tile, buffer 0)
    float* accB = xch + NN*VPAD;    // buffer 1: partial-acc exchange
    float* Wg1s = xch + NN*VPAD;    // 1024 (staged AFTER accB consumed)
    float* Wg2s = Wg1s + HP*HG;     // 1024
    float* bg1s = Wg2s + HG*DPE;    // 64
    float* bg2s = bg1s + HG;        // 16

    int b = blockIdx.x;
    int t = threadIdx.x;             // 0..511
    int node = t & 255;
    int s    = t >> 8;               // offset-split index

    // ---- Stage V tile [256 x 16] ----
    const float4* vg = (const float4*)(V + (size_t)b*NN*DPE);
    #pragma unroll
    for (int i = t; i < NN*DPE/4; i += 512) {
        float4 v = vg[i];
        *(float4*)&Vs[(i >> 2)*VPAD + ((i & 3) << 2)] = v;
    }

    // ---- psi MLP (t<64) + eigen-count binary search (t<2) ----
    float pacc = 0.f;
    if (t < DPE*MM) {
        int d = t >> 2, m = t & 3;
        float lam = Lambda[b*DPE + d];
        pacc = pb2[m];
        #pragma unroll
        for (int h = 0; h < HPSI; h++) {
            float v = fmaf(lam, pW1[m*HPSI + h], pb1[m*HPSI + h]);
            pacc = fmaf(fmaxf(v, 0.f), pW2[m*HPSI + h], pacc);
        }
    }
    if (t < 2) {
        int key = b + t;
        int lo = 0, hi = NSUM;
        while (lo < hi) {
            int mid = (lo + hi) >> 1;
            if (batch[mid] < key) lo = mid + 1; else hi = mid;
        }
        bnds[t] = lo;
    }

    // ---- Projection weights, packed, in registers ----
    u64 wp2[MM][HP/2];
    u64 bps2[HP/2];
    #pragma unroll
    for (int m = 0; m < MM; m++)
        #pragma unroll
        for (int hp = 0; hp < HP/2; hp++)
            wp2[m][hp] = pk2(Wp1[m*HP + 2*hp], Wp1[m*HP + 2*hp + 1]);
    #pragma unroll
    for (int hp = 0; hp < HP/2; hp++) bps2[hp] = pk2(bp1[2*hp], bp1[2*hp+1]);

    // ---- CSR build (512-thread version; temps aliased into xch) ----
    if (t < NN) cnt[t] = 0;
    __syncthreads();

    const int* srcp = edge_index + (size_t)b*EPG;
    const int* dstp = edge_index + (size_t)EDGES + (size_t)b*EPG;
    int base = b*NN;

    #pragma unroll
    for (int e = t; e < EPG; e += 512) {
        int d = dstp[e] - base;
        dstc[e] = d;
        atomicAdd(&cnt[d], 1);
    }
    __syncthreads();

    {
        int v = (t < NN) ? cnt[t] : 0;
        int incl = v;
        #pragma unroll
        for (int off = 1; off < 32; off <<= 1) {
            int x = __shfl_up_sync(0xffffffffu, incl, off);
            if ((t & 31) >= off) incl += x;
        }
        if (t < NN && (t & 31) == 31) wsum[t >> 5] = incl;
        __syncthreads();
        if (t == 0) {
            int ssum = 0;
            #pragma unroll
            for (int i = 0; i < 8; i++) { int x = wsum[i]; wsum[i] = ssum; ssum += x; }
        }
        __syncthreads();
        if (t < NN) {
            int excl = incl - v + wsum[t >> 5];
            start_s[t] = excl;
            cur[t] = excl;
        }
        if (t == 0) start_s[NN] = EPG;
    }
    __syncthreads();

    #pragma unroll
    for (int e = t; e < EPG; e += 512) {
        int pos = atomicAdd(&cur[dstc[e]], 1);
        srt_s[pos] = srcp[e] - base;
    }

    // ---- masked Z ----
    if (t < DPE*MM) {
        int c = bnds[1] - bnds[0];
        zs[t] = ((t >> 2) < c) ? pacc : 0.f;
    }
    __syncthreads();   // zs + srt_s visible; CSR temps done

    // ---- Per-thread packed scaled row (both s-threads of a node: same An2) ----
    u64 An2[MM][DPE/2];
    {
        const float4* vrow = (const float4*)&Vs[node*VPAD];
        #pragma unroll
        for (int q = 0; q < 4; q++) {
            float4 vv = vrow[q];
            #pragma unroll
            for (int m = 0; m < MM; m++) {
                An2[m][2*q]   = pk2(vv.x * zs[(4*q)*MM + m],   vv.y * zs[(4*q+1)*MM + m]);
                An2[m][2*q+1] = pk2(vv.z * zs[(4*q+2)*MM + m], vv.w * zs[(4*q+3)*MM + m]);
            }
        }
    }

    u64 acc2[HP/2];
    #pragma unroll
    for (int h = 0; h < HP/2; h++) acc2[h] = 0ull;

    u64 rp[8];

    // o = 0: diagonal pair (n,n) counted once — s==0 threads only
    if (s == 0) {
        COMPUTE_R2(node);
        #pragma unroll
        for (int h = 0; h < 8; h++) acc2[h] = add2(acc2[h], rp[h]);
    }

    float* xchLo = xch;
    float* xchHi = xch + 4*NN*VPAD;
    int jb = 2*s;    // my buffer indices: jb, jb+1

    // MAIN LOOP: 31 branch-free groups; this thread does offsets
    // o1 = 4g+1+2s, o2 = o1+1 (o in 1..124).
    for (int g = 0; g < 31; g++) {
        float* bufs = (g & 1) ? xchHi : xchLo;
        int o1 = 4*g + 1 + 2*s;
        BODY_WRITE(o1,     &bufs[jb*NN*VPAD + node*VPAD]);
        BODY_WRITE(o1 + 1, &bufs[(jb+1)*NN*VPAD + node*VPAD]);
        __syncthreads();
        BODY_READ(o1,     &bufs[jb*NN*VPAD]);
        BODY_READ(o1 + 1, &bufs[(jb+1)*NN*VPAD]);
    }

    // PEELED FINAL GROUP (g = 31, odd -> xchHi): s=0 does 125,126; s=1 does 127,128.
    {
        float* bufs = xchHi;
        int o1 = 125 + 2*s;
        BODY_WRITE(o1, &bufs[jb*NN*VPAD + node*VPAD]);
        if (s == 0) {
            BODY_WRITE(126, &bufs[1*NN*VPAD + node*VPAD]);
        } else if (node < 128) {   // o = 128: lower half computes
            BODY_WRITE(128, &bufs[3*NN*VPAD + node*VPAD]);
        }
        __syncthreads();
        BODY_READ(o1, &bufs[jb*NN*VPAD]);
        if (s == 0) {
            BODY_READ(126, &bufs[1*NN*VPAD]);
        } else if (node >= 128) {  // o = 128: upper half reads partner result
            BODY_READ(128, &bufs[3*NN*VPAD]);
        }
    }

    // ---- Combine partial accumulators of the two s-threads ----
    if (s == 1) {
        u64* aw = (u64*)&accB[node*VPAD];
        #pragma unroll
        for (int h = 0; h < 8; h++) aw[h] = acc2[h];
    }
    __syncthreads();
    if (s == 0) {
        const ulonglong2* ar = (const ulonglong2*)&accB[node*VPAD];
        ulonglong2 a0 = ar[0], a1 = ar[1], a2 = ar[2], a3 = ar[3];
        acc2[0] = add2(acc2[0], a0.x); acc2[1] = add2(acc2[1], a0.y);
        acc2[2] = add2(acc2[2], a1.x); acc2[3] = add2(acc2[3], a1.y);
        acc2[4] = add2(acc2[4], a2.x); acc2[5] = add2(acc2[5], a2.y);
        acc2[6] = add2(acc2[6], a3.x); acc2[7] = add2(acc2[7], a3.y);
        // write final x row into xT (buffer 0)
        ulonglong2* xw = (ulonglong2*)&xT[node*VPAD];
        xw[0] = make_ulonglong2(acc2[0], acc2[1]);
        xw[1] = make_ulonglong2(acc2[2], acc2[3]);
        xw[2] = make_ulonglong2(acc2[4], acc2[5]);
        xw[3] = make_ulonglong2(acc2[6], acc2[7]);
    }
    __syncthreads();   // xT complete; accB consumed -> region reusable for weights

    // ---- Stage GIN weights (into buffer-1 region) ----
    #pragma unroll
    for (int i = t; i < HP*HG; i += 512)  Wg1s[i] = Wg1[i];
    #pragma unroll
    for (int i = t; i < HG*DPE; i += 512) Wg2s[i] = Wg2[i];
    if (t < HG)  bg1s[t] = bg1[t];
    if (t >= 512 - DPE) bg2s[t - (512 - DPE)] = bg2[t - (512 - DPE)];
    float ge = 1.f + eps[0];
    __syncthreads();

    // ---- Epilogue: channel-split, 2 threads per node: node_e = t>>1 ----
    int node_e = t >> 1;
    int half   = t & 1;

    // GIN gather: my 8 channels over all my node's edges
    u64 agg[4];
    agg[0] = agg[1] = agg[2] = agg[3] = 0ull;
    {
        int s0 = start_s[node_e], s1 = start_s[node_e + 1];
        int idx = s0;
        for (; idx + 2 <= s1; idx += 2) {
            int ea = srt_s[idx], eb = srt_s[idx + 1];
            const ulonglong2* ra = (const ulonglong2*)&xT[ea*VPAD + 8*half];
            const ulonglong2* rb = (const ulonglong2*)&xT[eb*VPAD + 8*half];
            ulonglong2 a0 = ra[0], a1 = ra[1];
            ulonglong2 b0 = rb[0], b1 = rb[1];
            agg[0] = add2(agg[0], a0.x); agg[1] = add2(agg[1], a0.y);
            agg[2] = add2(agg[2], a1.x); agg[3] = add2(agg[3], a1.y);
            agg[0] = add2(agg[0], b0.x); agg[1] = add2(agg[1], b0.y);
            agg[2] = add2(agg[2], b1.x); agg[3] = add2(agg[3], b1.y);
        }
        if (idx < s1) {
            int e = srt_s[idx];
            const ulonglong2* r = (const ulonglong2*)&xT[e*VPAD + 8*half];
            ulonglong2 q0 = r[0], q1 = r[1];
            agg[0] = add2(agg[0], q0.x); agg[1] = add2(agg[1], q0.y);
            agg[2] = add2(agg[2], q1.x); agg[3] = add2(agg[3], q1.y);
        }
    }

    // y (my 8 channels) = (1+eps)*x_self + agg
    u64 ge2 = pk2(ge, ge);
    u64 ymine[4];
    {
        const ulonglong2* xself = (const ulonglong2*)&xT[node_e*VPAD + 8*half];
        ulonglong2 p0 = xself[0], p1 = xself[1];
        ymine[0] = fma2(ge2, p0.x, agg[0]); ymine[1] = fma2(ge2, p0.y, agg[1]);
        ymine[2] = fma2(ge2, p1.x, agg[2]); ymine[3] = fma2(ge2, p1.y, agg[3]);
    }
    // Full y via lane-pair shuffle
    u64 yfull[8];
    #pragma unroll
    for (int j = 0; j < 4; j++) {
        u64 yo = __shfl_xor_sync(0xffffffffu, ymine[j], 1);
        yfull[4*half + j]     = ymine[j];
        yfull[4*(1-half) + j] = yo;
    }

    // Layer 1: my 32 output columns = [32*half, 32*half+32)
    u64 tg[16];
    {
        const u64* bu = (const u64*)bg1s;
        #pragma unroll
        for (int j = 0; j < 16; j++) tg[j] = bu[16*half + j];
    }
    #pragma unroll
    for (int hq = 0; hq < 8; hq++) {
        float ylo, yhi; upk2(yfull[hq], ylo, yhi);
        u64 ya = pk2(ylo, ylo), yb = pk2(yhi, yhi);
        const u64* wa = (const u64*)&Wg1s[(2*hq)*HG   + 32*half];
        const u64* wb = (const u64*)&Wg1s[(2*hq+1)*HG + 32*half];
        #pragma unroll
        for (int j = 0; j < 16; j++) {
            tg[j] = fma2(ya, wa[j], tg[j]);
            tg[j] = fma2(yb, wb[j], tg[j]);
        }
    }

    // ReLU + layer 2 partial over my 32 T-rows
    u64 o2[8];
    {
        const u64* bu = (const u64*)bg2s;
        #pragma unroll
        for (int d = 0; d < 8; d++) o2[d] = half ? 0ull : bu[d];
    }
    #pragma unroll
    for (int j = 0; j < 16; j++) {
        float t0, t1; upk2(tg[j], t0, t1);
        t0 = fmaxf(t0, 0.f); t1 = fmaxf(t1, 0.f);
        u64 ta = pk2(t0, t0), tb = pk2(t1, t1);
        int r0 = 32*half + 2*j;
        const u64* wa = (const u64*)&Wg2s[r0*DPE];
        const u64* wb = (const u64*)&Wg2s[(r0+1)*DPE];
        #pragma unroll
        for (int d = 0; d < 8; d++) {
            o2[d] = fma2(ta, wa[d], o2[d]);
            o2[d] = fma2(tb, wb[d], o2[d]);
        }
    }
    // Reduce across the lane pair
    #pragma unroll
    for (int d = 0; d < 8; d++) {
        u64 oo = __shfl_xor_sync(0xffffffffu, o2[d], 1);
        o2[d] = add2(o2[d], oo);
    }

    if (half == 0) {
        ulonglong2* op = (ulonglong2*)(out + (size_t)(b*NN + node_e)*DPE);
        op[0] = make_ulonglong2(o2[0], o2[1]);
        op[1] = make_ulonglong2(o2[2], o2[3]);
        op[2] = make_ulonglong2(o2[4], o2[5]);
        op[3] = make_ulonglong2(o2[6], o2[7]);
    }
}

// ---------------------------------------------------------------------------
extern "C" void kernel_launch(void* const* d_in, const int* in_sizes, int n_in,
                              void* d_out, int out_size)
{
    const float* Lambda = (const float*)d_in[0];
    const float* V      = (const float*)d_in[1];
    const float* pW1    = (const float*)d_in[2];
    const float* pb1    = (const float*)d_in[3];
    const float* pW2    = (const float*)d_in[4];
    const float* pb2    = (const float*)d_in[5];
    const float* Wp1    = (const float*)d_in[6];
    const float* bp1    = (const float*)d_in[7];
    const float* Wg1    = (const float*)d_in[8];
    const float* bg1    = (const float*)d_in[9];
    const float* Wg2    = (const float*)d_in[10];
    const float* bg2    = (const float*)d_in[11];
    const float* eps    = (const float*)d_in[12];
    const int*   edge_index = (const int*)d_in[13];
    const int*   batch  = (const int*)d_in[14];
    float* out = (float*)d_out;

    const int smemF = (9*NN*VPAD + 64 + 4096 + 257 + 3) * (int)sizeof(float); // 202060 B
    cudaFuncSetAttribute(kernelF, cudaFuncAttributeMaxDynamicSharedMemorySize, smemF);

    kernelF<<<NB, 512, smemF>>>(V, Lambda, pW1, pb1, pW2, pb2, Wp1, bp1,
                                Wg1, bg1, Wg2, bg2, eps, batch, edge_index, out);
}

// round 16
// speedup vs baseline: 1.0651x; 1.0651x over previous
#include <cuda_runtime.h>

// Problem constants (fixed by the dataset)
#define NB    128          // graphs (B)
#define NN    256          // nodes per graph
#define DPE   16           // D_pe / eigen dim
#define MM    4            // M psi copies
#define HPSI  32
#define HP    16
#define HG    64
#define NSUM  (NB*NN)      // 32768
#define EDGES (NSUM*16)    // 524288
#define EPG   (EDGES/NB)   // 4096 edges per graph (graph-contiguous)
#define VPAD  20           // padded row stride (floats)

typedef unsigned long long u64;

// ---------------- packed f32x2 helpers ----------------
__device__ __forceinline__ u64 pk2(float lo, float hi) {
    u64 r; asm("mov.b64 %0,{%1,%2};" : "=l"(r) : "f"(lo), "f"(hi)); return r;
}
__device__ __forceinline__ void upk2(u64 v, float& lo, float& hi) {
    asm("mov.b64 {%0,%1},%2;" : "=f"(lo), "=f"(hi) : "l"(v));
}
__device__ __forceinline__ u64 fma2(u64 a, u64 b, u64 c) {
    u64 d; asm("fma.rn.f32x2 %0,%1,%2,%3;" : "=l"(d) : "l"(a), "l"(b), "l"(c)); return d;
}
__device__ __forceinline__ u64 mul2(u64 a, u64 b) {
    u64 d; asm("mul.rn.f32x2 %0,%1,%2;" : "=l"(d) : "l"(a), "l"(b)); return d;
}
__device__ __forceinline__ u64 add2(u64 a, u64 b) {
    u64 d; asm("add.rn.f32x2 %0,%1,%2;" : "=l"(d) : "l"(a), "l"(b)); return d;
}

// ---------------------------------------------------------------------------
// ONE fused kernel per graph (R14 base): CSR build -> psi/mask -> pairwise
// o-loop (31 branch-free groups of 4 + peeled final) -> in-smem GIN + MLP.
// V tile REPLICATED to 512 rows so the o-loop gather needs no (&255) wrap:
// row pointer is affine in o -> strength-reduced addressing.
// ---------------------------------------------------------------------------
#define COMPUTE_R2(kk) do {                                                     \
    const ulonglong2* vr_ = (const ulonglong2*)&Vs[(kk)*VPAD];                  \
    ulonglong2 a_ = vr_[0], b_ = vr_[1], c_ = vr_[2], d_ = vr_[3];              \
    u64 vk_[8] = {a_.x, a_.y, b_.x, b_.y, c_.x, c_.y, d_.x, d_.y};              \
    u64 wm_[4];                                                                 \
    _Pragma("unroll")                                                           \
    for (int m_ = 0; m_ < 4; m_++) {                                            \
        u64 s_ = mul2(An2[m_][0], vk_[0]);                                      \
        _Pragma("unroll")                                                       \
        for (int j_ = 1; j_ < 8; j_++) s_ = fma2(An2[m_][j_], vk_[j_], s_);     \
        float lo_, hi_; upk2(s_, lo_, hi_);                                     \
        float w_ = lo_ + hi_;                                                   \
        wm_[m_] = pk2(w_, w_);                                                  \
    }                                                                           \
    _Pragma("unroll")                                                           \
    for (int hp_ = 0; hp_ < 8; hp_++) {                                         \
        u64 p_ = fma2(wm_[0], wp2[0][hp_], bps2[hp_]);                          \
        p_ = fma2(wm_[1], wp2[1][hp_], p_);                                     \
        p_ = fma2(wm_[2], wp2[2][hp_], p_);                                     \
        p_ = fma2(wm_[3], wp2[3][hp_], p_);                                     \
        float lo_, hi_; upk2(p_, lo_, hi_);                                     \
        lo_ = fmaxf(lo_, 0.f); hi_ = fmaxf(hi_, 0.f);                           \
        rp[hp_] = pk2(lo_, hi_);                                                \
    }                                                                           \
} while (0)

__global__ void __launch_bounds__(256) kernelF(
        const float* __restrict__ V,
        const float* __restrict__ Lambda,
        const float* __restrict__ pW1, const float* __restrict__ pb1,
        const float* __restrict__ pW2, const float* __restrict__ pb2,
        const float* __restrict__ Wp1, const float* __restrict__ bp1,
        const float* __restrict__ Wg1, const float* __restrict__ bg1,
        const float* __restrict__ Wg2, const float* __restrict__ bg2,
        const float* __restrict__ eps,
        const int*   __restrict__ batch,
        const int*   __restrict__ edge_index,
        float* __restrict__ out)
{
    extern __shared__ float sm[];
    // Persistent regions
    float* Vs      = sm;                          // 2*NN*VPAD floats (replicated)
    float* xch     = sm + 2*NN*VPAD;              // 8 buffers x 5120
    float* zs      = sm + 10*NN*VPAD;             // 64
    int*   srt_s   = (int*)(sm + 10*NN*VPAD + 64);        // 4096 ints
    int*   start_s = (int*)(sm + 10*NN*VPAD + 64 + 4096); // 257 ints
    __shared__ int bnds[2];
    __shared__ int wsum[8];

    // Phase-limited aliases (CSR build) inside xch:
    int* cnt  = (int*)xch;          // 256
    int* cur  = cnt + NN;           // 256
    int* dstc = cur + NN;           // 4096

    // Phase-limited aliases (epilogue) inside xch:
    float* xT   = xch;              // 5120 (x tile)
    float* Wg1s = xch + NN*VPAD;    // 1024
    float* Wg2s = Wg1s + HP*HG;     // 1024
    float* bg1s = Wg2s + HG*DPE;    // 64
    float* bg2s = bg1s + HG;        // 16

    int b = blockIdx.x;
    int n = threadIdx.x;

    // ---- Stage V tile [256 x 16] into padded smem, REPLICATED (row n+256=n) ----
    const float4* vg = (const float4*)(V + (size_t)b*NN*DPE);
    for (int i = n; i < NN*DPE/4; i += 256) {
        float4 v = vg[i];
        int row = i >> 2, col = (i & 3) << 2;
        *(float4*)&Vs[row*VPAD + col] = v;
        *(float4*)&Vs[(row + NN)*VPAD + col] = v;
    }

    // ---- psi MLP (threads 0..63) + eigen-count binary search (threads 0,1) ----
    float pacc = 0.f;
    if (n < DPE*MM) {
        int d = n >> 2, m = n & 3;
        float lam = Lambda[b*DPE + d];
        pacc = pb2[m];
        #pragma unroll
        for (int h = 0; h < HPSI; h++) {
            float v = fmaf(lam, pW1[m*HPSI + h], pb1[m*HPSI + h]);
            pacc = fmaf(fmaxf(v, 0.f), pW2[m*HPSI + h], pacc);
        }
    }
    if (n < 2) {
        int key = b + n;            // first index with batch[i] >= key
        int lo = 0, hi = NSUM;
        while (lo < hi) {
            int mid = (lo + hi) >> 1;
            if (batch[mid] < key) lo = mid + 1; else hi = mid;
        }
        bnds[n] = lo;
    }

    // ---- Projection weights, packed, in registers ----
    u64 wp2[MM][HP/2];
    u64 bps2[HP/2];
    #pragma unroll
    for (int m = 0; m < MM; m++)
        #pragma unroll
        for (int hp = 0; hp < HP/2; hp++)
            wp2[m][hp] = pk2(Wp1[m*HP + 2*hp], Wp1[m*HP + 2*hp + 1]);
    #pragma unroll
    for (int hp = 0; hp < HP/2; hp++) bps2[hp] = pk2(bp1[2*hp], bp1[2*hp+1]);

    // ---- CSR build (uses cnt/cur/dstc aliased into xch) ----
    cnt[n] = 0;
    __syncthreads();

    const int* srcp = edge_index + (size_t)b*EPG;
    const int* dstp = edge_index + (size_t)EDGES + (size_t)b*EPG;
    int base = b*NN;

    #pragma unroll
    for (int e = n; e < EPG; e += 256) {
        int d = dstp[e] - base;
        dstc[e] = d;
        atomicAdd(&cnt[d], 1);
    }
    __syncthreads();

    {
        int v = cnt[n];
        int incl = v;
        #pragma unroll
        for (int off = 1; off < 32; off <<= 1) {
            int x = __shfl_up_sync(0xffffffffu, incl, off);
            if ((n & 31) >= off) incl += x;
        }
        if ((n & 31) == 31) wsum[n >> 5] = incl;
        __syncthreads();
        if (n == 0) {
            int s = 0;
            #pragma unroll
            for (int i = 0; i < 8; i++) { int x = wsum[i]; wsum[i] = s; s += x; }
        }
        __syncthreads();
        int excl = incl - v + wsum[n >> 5];
        start_s[n] = excl;
        if (n == 0) start_s[NN] = EPG;
        cur[n] = excl;
    }
    __syncthreads();

    #pragma unroll
    for (int e = n; e < EPG; e += 256) {
        int pos = atomicAdd(&cur[dstc[e]], 1);
        srt_s[pos] = srcp[e] - base;
    }

    // ---- masked Z ----
    if (n < DPE*MM) {
        int c = bnds[1] - bnds[0];
        zs[n] = ((n >> 2) < c) ? pacc : 0.f;
    }
    __syncthreads();   // zs + srt_s visible; CSR temps (in xch) done

    // ---- Per-thread packed scaled row ----
    u64 An2[MM][DPE/2];
    {
        const float4* vrow = (const float4*)&Vs[n*VPAD];
        #pragma unroll
        for (int q = 0; q < 4; q++) {
            float4 vv = vrow[q];
            #pragma unroll
            for (int m = 0; m < MM; m++) {
                An2[m][2*q]   = pk2(vv.x * zs[(4*q)*MM + m],   vv.y * zs[(4*q+1)*MM + m]);
                An2[m][2*q+1] = pk2(vv.z * zs[(4*q+2)*MM + m], vv.w * zs[(4*q+3)*MM + m]);
            }
        }
    }

    u64 acc2[HP/2];
    #pragma unroll
    for (int h = 0; h < HP/2; h++) acc2[h] = 0ull;

    u64 rp[8];

    // o = 0: diagonal pair (n,n) counted once
    {
        COMPUTE_R2(n);
        #pragma unroll
        for (int h = 0; h < 8; h++) acc2[h] = add2(acc2[h], rp[h]);
    }

    float* xchLo = xch;
    float* xchHi = xch + 4*NN*VPAD;

    // MAIN LOOP: 31 branch-free groups of 4 offsets (o = 1..124).
    // Gather row index k = n + o (replicated tile, no wrap).
    for (int g = 0; g < 31; g++) {
        float* bufs = (g & 1) ? xchHi : xchLo;

        #pragma unroll
        for (int j = 0; j < 4; j++) {
            int o = 4*g + 1 + j;
            int k = n + o;                      // no mask: replicated V rows
            COMPUTE_R2(k);
            u64* xw = (u64*)&bufs[j*NN*VPAD + n*VPAD];
            #pragma unroll
            for (int h = 0; h < 8; h++) {
                acc2[h] = add2(acc2[h], rp[h]);
                xw[h] = rp[h];
            }
        }
        __syncthreads();
        #pragma unroll
        for (int j = 0; j < 4; j++) {
            int o = 4*g + 1 + j;
            int p = (n - o) & 255;
            const ulonglong2* xr = (const ulonglong2*)&bufs[j*NN*VPAD + p*VPAD];
            ulonglong2 a0 = xr[0], a1 = xr[1], a2 = xr[2], a3 = xr[3];
            acc2[0] = add2(acc2[0], a0.x); acc2[1] = add2(acc2[1], a0.y);
            acc2[2] = add2(acc2[2], a1.x); acc2[3] = add2(acc2[3], a1.y);
            acc2[4] = add2(acc2[4], a2.x); acc2[5] = add2(acc2[5], a2.y);
            acc2[6] = add2(acc2[6], a3.x); acc2[7] = add2(acc2[7], a3.y);
        }
    }

    // PEELED FINAL GROUP: offsets 125, 126, 127 (unconditional) + 128 (half).
    {
        float* bufs = xchHi;     // g = 31 is odd
        #pragma unroll
        for (int j = 0; j < 3; j++) {
            int o = 125 + j;
            int k = n + o;
            COMPUTE_R2(k);
            u64* xw = (u64*)&bufs[j*NN*VPAD + n*VPAD];
            #pragma unroll
            for (int h = 0; h < 8; h++) {
                acc2[h] = add2(acc2[h], rp[h]);
                xw[h] = rp[h];
            }
        }
        if (n < 128) {           // o = 128: lower half computes
            int k = n + 128;
            COMPUTE_R2(k);
            u64* xw = (u64*)&bufs[3*NN*VPAD + n*VPAD];
            #pragma unroll
            for (int h = 0; h < 8; h++) {
                acc2[h] = add2(acc2[h], rp[h]);
                xw[h] = rp[h];
            }
        }
        __syncthreads();
        #pragma unroll
        for (int j = 0; j < 3; j++) {
            int o = 125 + j;
            int p = (n - o) & 255;
            const ulonglong2* xr = (const ulonglong2*)&bufs[j*NN*VPAD + p*VPAD];
            ulonglong2 a0 = xr[0], a1 = xr[1], a2 = xr[2], a3 = xr[3];
            acc2[0] = add2(acc2[0], a0.x); acc2[1] = add2(acc2[1], a0.y);
            acc2[2] = add2(acc2[2], a1.x); acc2[3] = add2(acc2[3], a1.y);
            acc2[4] = add2(acc2[4], a2.x); acc2[5] = add2(acc2[5], a2.y);
            acc2[6] = add2(acc2[6], a3.x); acc2[7] = add2(acc2[7], a3.y);
        }
        if (n >= 128) {          // o = 128: upper half reads partner result
            int p = (n - 128) & 255;
            const ulonglong2* xr = (const ulonglong2*)&bufs[3*NN*VPAD + p*VPAD];
            ulonglong2 a0 = xr[0], a1 = xr[1], a2 = xr[2], a3 = xr[3];
            acc2[0] = add2(acc2[0], a0.x); acc2[1] = add2(acc2[1], a0.y);
            acc2[2] = add2(acc2[2], a1.x); acc2[3] = add2(acc2[3], a1.y);
            acc2[4] = add2(acc2[4], a2.x); acc2[5] = add2(acc2[5], a2.y);
            acc2[6] = add2(acc2[6], a3.x); acc2[7] = add2(acc2[7], a3.y);
        }
    }
    __syncthreads();   // all exchange reads complete; xch reusable

    // ---- Epilogue: write x tile, stage GIN weights (alias into xch) ----
    {
        ulonglong2* xw = (ulonglong2*)&xT[n*VPAD];
        xw[0] = make_ulonglong2(acc2[0], acc2[1]);
        xw[1] = make_ulonglong2(acc2[2], acc2[3]);
        xw[2] = make_ulonglong2(acc2[4], acc2[5]);
        xw[3] = make_ulonglong2(acc2[6], acc2[7]);
    }
    #pragma unroll
    for (int i = n; i < HP*HG; i += 256)  Wg1s[i] = Wg1[i];
    #pragma unroll
    for (int i = n; i < HG*DPE; i += 256) Wg2s[i] = Wg2[i];
    if (n < HG)  bg1s[n] = bg1[n];
    if (n >= 256 - DPE) bg2s[n - (256 - DPE)] = bg2[n - (256 - DPE)];
    float ge = 1.f + eps[0];
    __syncthreads();

    // ---- GIN gather (in-smem CSR) ----
    u64 agg[8];
    #pragma unroll
    for (int j = 0; j < 8; j++) agg[j] = 0ull;
    {
        int s0 = start_s[n], s1 = start_s[n + 1];
        int idx = s0;
        for (; idx + 2 <= s1; idx += 2) {
            int ea = srt_s[idx], eb = srt_s[idx + 1];
            const ulonglong2* ra = (const ulonglong2*)&xT[ea*VPAD];
            const ulonglong2* rb = (const ulonglong2*)&xT[eb*VPAD];
            ulonglong2 a0=ra[0], a1=ra[1], a2=ra[2], a3=ra[3];
            ulonglong2 b0=rb[0], b1=rb[1], b2=rb[2], b3=rb[3];
            agg[0]=add2(agg[0],a0.x); agg[1]=add2(agg[1],a0.y);
            agg[2]=add2(agg[2],a1.x); agg[3]=add2(agg[3],a1.y);
            agg[4]=add2(agg[4],a2.x); agg[5]=add2(agg[5],a2.y);
            agg[6]=add2(agg[6],a3.x); agg[7]=add2(agg[7],a3.y);
            agg[0]=add2(agg[0],b0.x); agg[1]=add2(agg[1],b0.y);
            agg[2]=add2(agg[2],b1.x); agg[3]=add2(agg[3],b1.y);
            agg[4]=add2(agg[4],b2.x); agg[5]=add2(agg[5],b2.y);
            agg[6]=add2(agg[6],b3.x); agg[7]=add2(agg[7],b3.y);
        }
        if (idx < s1) {
            int e = srt_s[idx];
            const ulonglong2* r = (const ulonglong2*)&xT[e*VPAD];
            ulonglong2 q0=r[0], q1=r[1], q2=r[2], q3=r[3];
            agg[0]=add2(agg[0],q0.x); agg[1]=add2(agg[1],q0.y);
            agg[2]=add2(agg[2],q1.x); agg[3]=add2(agg[3],q1.y);
            agg[4]=add2(agg[4],q2.x); agg[5]=add2(agg[5],q2.y);
            agg[6]=add2(agg[6],q3.x); agg[7]=add2(agg[7],q3.y);
        }
    }

    // y = (1+eps)*x_self + agg  (x_self = acc2 still in registers)
    u64 ge2 = pk2(ge, ge);
    u64 yfull[8];
    #pragma unroll
    for (int j = 0; j < 8; j++) yfull[j] = fma2(ge2, acc2[j], agg[j]);

    // Layer 1: tg[64] = y @ Wg1 + bg1 (full, per thread)
    u64 tg[HG/2];
    {
        const u64* bu = (const u64*)bg1s;
        #pragma unroll
        for (int j = 0; j < HG/2; j++) tg[j] = bu[j];
    }
    #pragma unroll
    for (int hq = 0; hq < 8; hq++) {
        float ylo, yhi; upk2(yfull[hq], ylo, yhi);
        u64 ya = pk2(ylo, ylo), yb = pk2(yhi, yhi);
        const u64* wa = (const u64*)&Wg1s[(2*hq)*HG];
        const u64* wb = (const u64*)&Wg1s[(2*hq+1)*HG];
        #pragma unroll
        for (int j = 0; j < HG/2; j++) {
            tg[j] = fma2(ya, wa[j], tg[j]);
            tg[j] = fma2(yb, wb[j], tg[j]);
        }
    }

    // ReLU + layer 2: out[16] = relu(tg) @ Wg2 + bg2
    u64 o2[DPE/2];
    {
        const u64* bu = (const u64*)bg2s;
        #pragma unroll
        for (int d = 0; d < DPE/2; d++) o2[d] = bu[d];
    }
    #pragma unroll
    for (int j = 0; j < HG/2; j++) {
        float t0, t1; upk2(tg[j], t0, t1);
        t0 = fmaxf(t0, 0.f); t1 = fmaxf(t1, 0.f);
        u64 ta = pk2(t0, t0), tb = pk2(t1, t1);
        const u64* wa = (const u64*)&Wg2s[(2*j)*DPE];
        const u64* wb = (const u64*)&Wg2s[(2*j+1)*DPE];
        #pragma unroll
        for (int d = 0; d < DPE/2; d++) {
            o2[d] = fma2(ta, wa[d], o2[d]);
            o2[d] = fma2(tb, wb[d], o2[d]);
        }
    }

    ulonglong2* op = (ulonglong2*)(out + (size_t)(b*NN + n)*DPE);
    op[0] = make_ulonglong2(o2[0], o2[1]);
    op[1] = make_ulonglong2(o2[2], o2[3]);
    op[2] = make_ulonglong2(o2[4], o2[5]);
    op[3] = make_ulonglong2(o2[6], o2[7]);
}

// ---------------------------------------------------------------------------
extern "C" void kernel_launch(void* const* d_in, const int* in_sizes, int n_in,
                              void* d_out, int out_size)
{
    const float* Lambda = (const float*)d_in[0];
    const float* V      = (const float*)d_in[1];
    const float* pW1    = (const float*)d_in[2];
    const float* pb1    = (const float*)d_in[3];
    const float* pW2    = (const float*)d_in[4];
    const float* pb2    = (const float*)d_in[5];
    const float* Wp1    = (const float*)d_in[6];
    const float* bp1    = (const float*)d_in[7];
    const float* Wg1    = (const float*)d_in[8];
    const float* bg1    = (const float*)d_in[9];
    const float* Wg2    = (const float*)d_in[10];
    const float* bg2    = (const float*)d_in[11];
    const float* eps    = (const float*)d_in[12];
    const int*   edge_index = (const int*)d_in[13];
    const int*   batch  = (const int*)d_in[14];
    float* out = (float*)d_out;

    // Vs(2*5120) + xch(8*5120) + zs(64) + srt(4096) + start(257+3) floats
    const int smemF = (10*NN*VPAD + 64 + 4096 + 257 + 3) * (int)sizeof(float); // 222540 B
    cudaFuncSetAttribute(kernelF, cudaFuncAttributeMaxDynamicSharedMemorySize, smemF);

    kernelF<<<NB, 256, smemF>>>(V, Lambda, pW1, pb1, pW2, pb2, Wp1, bp1,
                                Wg1, bg1, Wg2, bg2, eps, batch, edge_index, out);
}